// round 13
// baseline (speedup 1.0000x reference)
#include <cuda_runtime.h>
#include <cuda_fp16.h>
#include <cstdint>
#include <cstddef>
#include <math.h>

// ---------------------------------------------------------------------------
#define BB 2
#define HH 16
#define TT 2048
#define DD 2048
#define HD 128
#define KK 2048
#define MM 4096
#define SCALE 0.08838834764831845f
#define CH (BB * HH * TT * HD)

// QKV stream-K-lite constants: 1536 tiles = 1480 full (5x296) + 56 tail
#define QKV_TILES 1536
#define QKV_FULL 1480
#define QKV_TAIL 56                    // all z=2 (V) tiles, y in 28..31
#define TAIL_UNITS (QKV_TAIL * 4)      // 224 quarter-K units

// ---------------------------------------------------------------------------
// Scratch (device globals; allocation is forbidden).  All single fp16.
// ---------------------------------------------------------------------------
__device__ __half g_hs[MM * KK];
__device__ __half g_enc[MM * KK];
__device__ __half g_wq[DD * KK];
__device__ __half g_wk[DD * KK];
__device__ __half g_wv[DD * KK];
__device__ __half g_wo[DD * KK];
__device__ __half g_q[CH];                  // [B,H,T,HD]
__device__ __half g_k[CH];                  // [B,H,S,HD]
__device__ __half g_v[CH];                  // [B,H,HD,S] transposed
__device__ __half g_c[MM * DD];             // ctx [B,T,D]
__device__ float  g_ws[TAIL_UNITS * 128 * 128];   // 14.7MB partials

// ---------------------------------------------------------------------------
// Helpers (baseline sm_80 features only)
// ---------------------------------------------------------------------------
__device__ __forceinline__ uint32_t smem_to_u32(const void* p) {
    uint32_t a;
    asm("{ .reg .u64 t; cvta.to.shared.u64 t, %1; cvt.u32.u64 %0, t; }" : "=r"(a) : "l"(p));
    return a;
}
__device__ __forceinline__ void cp_async16(uint32_t dst, const void* src) {
    asm volatile("cp.async.cg.shared.global [%0], [%1], 16;" :: "r"(dst), "l"(src));
}
#define CP_ASYNC_COMMIT() asm volatile("cp.async.commit_group;" ::: "memory")
#define CP_ASYNC_WAIT(n)  asm volatile("cp.async.wait_group %0;" :: "n"(n) : "memory")

__device__ __forceinline__ void ldm4(uint32_t* r, uint32_t addr) {
    asm volatile("ldmatrix.sync.aligned.m8n8.x4.shared.b16 {%0,%1,%2,%3}, [%4];"
                 : "=r"(r[0]), "=r"(r[1]), "=r"(r[2]), "=r"(r[3]) : "r"(addr));
}
__device__ __forceinline__ void mma16816(float* c, const uint32_t* a, uint32_t b0, uint32_t b1) {
    asm volatile("mma.sync.aligned.m16n8k16.row.col.f32.f16.f16.f32 "
                 "{%0,%1,%2,%3}, {%4,%5,%6,%7}, {%8,%9}, {%0,%1,%2,%3};"
                 : "+f"(c[0]), "+f"(c[1]), "+f"(c[2]), "+f"(c[3])
                 : "r"(a[0]), "r"(a[1]), "r"(a[2]), "r"(a[3]), "r"(b0), "r"(b1));
}
__device__ __forceinline__ uint32_t packhf(__half a, __half b) {
    __half2 t(a, b);
    return *reinterpret_cast<uint32_t*>(&t);
}

// ---------------------------------------------------------------------------
// Fused fp32 -> fp16 convert, 32 elements/thread
// ---------------------------------------------------------------------------
#define NAE ((size_t)MM * KK)
#define NWE ((size_t)DD * KK)
#define TOT_E (2 * NAE + 4 * NWE)

__global__ __launch_bounds__(256)
void conv_all(const float* __restrict__ hs, const float* __restrict__ enc,
              const float* __restrict__ wq, const float* __restrict__ wk,
              const float* __restrict__ wv, const float* __restrict__ wo,
              __half* __restrict__ hs_o, __half* __restrict__ enc_o,
              __half* __restrict__ wq_o, __half* __restrict__ wk_o,
              __half* __restrict__ wv_o, __half* __restrict__ wo_o)
{
    size_t e = ((size_t)blockIdx.x * 256 + threadIdx.x) * 32;
    if (e >= TOT_E) return;
    const float* src; __half* dst; size_t base;
    if      (e < NAE)            { src = hs;  dst = hs_o;  base = 0; }
    else if (e < 2 * NAE)        { src = enc; dst = enc_o; base = NAE; }
    else if (e < 2 * NAE + NWE)  { src = wq;  dst = wq_o;  base = 2 * NAE; }
    else if (e < 2 * NAE + 2 * NWE) { src = wk; dst = wk_o; base = 2 * NAE + NWE; }
    else if (e < 2 * NAE + 3 * NWE) { src = wv; dst = wv_o; base = 2 * NAE + 2 * NWE; }
    else                         { src = wo;  dst = wo_o;  base = 2 * NAE + 3 * NWE; }
    const size_t j = e - base;
    const float4* s4 = (const float4*)src + (j >> 2);
    uint4* d4 = (uint4*)dst + (j >> 3);
    #pragma unroll
    for (int v = 0; v < 4; ++v) {
        float4 a = s4[2 * v];
        float4 b = s4[2 * v + 1];
        uint4 o;
        o.x = packhf(__float2half(a.x), __float2half(a.y));
        o.y = packhf(__float2half(a.z), __float2half(a.w));
        o.z = packhf(__float2half(b.x), __float2half(b.y));
        o.w = packhf(__float2half(b.z), __float2half(b.w));
        d4[v] = o;
    }
}

// ---------------------------------------------------------------------------
// 1-pass fp16 GEMM core (128x128 CTA tile, BK=64, 4 warps 64x64, 3-stage
// ring, 2 CTAs/SM).  QKV=true uses a 1D grid of 1704 work items:
//   wi < 1480             : full tile (K = all 32 stages) + normal epilogue
//   wi >= 1480            : quarter-K unit of a tail V-tile -> fp32 partial
// QKV=false (O-proj): rectangular grid, unchanged.
// ---------------------------------------------------------------------------
#define TILE_B 18432                   // 128 rows * 144B
#define STAGE_B (2 * TILE_B)
#define SMEM_GEMM (3 * STAGE_B)        // 110592 -> 2 CTAs/SM
#define NSTAGES (KK / 64)              // 32
#define GTHREADS 128

__device__ __forceinline__ void load_stage_g(
    uint32_t sbuf, int s, int m0, int n0,
    const __half* __restrict__ A, const __half* __restrict__ W, int tid)
{
    const int k0 = s * 64;
    #pragma unroll
    for (int q = 0; q < 8; ++q) {
        const int id = tid + GTHREADS * q;
        const int r = id >> 3, c = id & 7;
        const uint32_t doff = r * 144 + c * 16;
        const size_t gA = (size_t)(m0 + r) * KK + k0 + c * 8;
        const size_t gW = (size_t)(n0 + r) * KK + k0 + c * 8;
        cp_async16(sbuf + doff,          A + gA);
        cp_async16(sbuf + TILE_B + doff, W + gW);
    }
}

template<bool QKV>
__global__ __launch_bounds__(GTHREADS, 2)
void gemm_kernel(const __half* __restrict__ a0, const __half* __restrict__ a1,
                 const __half* __restrict__ w0, const __half* __restrict__ w1,
                 const __half* __restrict__ w2,
                 const float* __restrict__ cq, const float* __restrict__ sq,
                 const float* __restrict__ ck, const float* __restrict__ sk,
                 __half* __restrict__ qo, __half* __restrict__ ko,
                 __half* __restrict__ vo,
                 float* __restrict__ ws,
                 float* __restrict__ fout)
{
    extern __shared__ __align__(128) uint8_t smem_raw[];
    const uint32_t sbase = smem_to_u32(smem_raw);
    const int tid = threadIdx.x;

    int m0, n0, z, s_lo, s_hi, uq;
    if (QKV) {
        const int wi = blockIdx.x;
        int tidx;
        if (wi < QKV_FULL) {
            tidx = wi; s_lo = 0; s_hi = NSTAGES; uq = -1;
        } else {
            const int u = wi - QKV_FULL;
            uq = u;
            tidx = QKV_FULL + (u >> 2);
            const int q = u & 3;
            s_lo = q * 8; s_hi = s_lo + 8;
        }
        const int x = tidx & 15;
        const int y = (tidx >> 4) & 31;
        z = tidx >> 9;
        m0 = y * 128; n0 = x * 128;
    } else {
        m0 = blockIdx.y * 128; n0 = blockIdx.x * 128;
        z = 0; s_lo = 0; s_hi = NSTAGES; uq = -1;
    }

    const __half *A, *W;
    if (QKV) {
        A = (z == 0) ? a0 : a1;
        W = (z == 0) ? w0 : (z == 1) ? w1 : w2;
    } else {
        A = a0; W = w0;
    }

    const int wid = tid >> 5, lid = tid & 31;
    const int wm = wid >> 1, wn = wid & 1;
    const int g = lid >> 2, t = lid & 3;
    const int lrow = lid & 15;
    const int lcolb = (lid >> 4) * 16;

    float acc[4][8][4];
    #pragma unroll
    for (int mt = 0; mt < 4; ++mt)
        #pragma unroll
        for (int nt = 0; nt < 8; ++nt)
            #pragma unroll
            for (int q = 0; q < 4; ++q) acc[mt][nt][q] = 0.0f;

    load_stage_g(sbase, s_lo, m0, n0, A, W, tid); CP_ASYNC_COMMIT();
    load_stage_g(sbase + STAGE_B, s_lo + 1, m0, n0, A, W, tid); CP_ASYNC_COMMIT();

    for (int s = s_lo; s < s_hi; ++s) {
        CP_ASYNC_WAIT(1);
        __syncthreads();
        if (s + 2 < s_hi) {
            int rel = s + 2 - s_lo;
            int bslot = rel - (rel / 3) * 3;
            load_stage_g(sbase + bslot * STAGE_B, s + 2, m0, n0, A, W, tid);
        }
        CP_ASYNC_COMMIT();

        const int rel = s - s_lo;
        const uint32_t buf = sbase + (rel % 3) * STAGE_B;
        const uint32_t aT = buf, bT = buf + TILE_B;

        #pragma unroll
        for (int kc = 0; kc < 4; ++kc) {
            const uint32_t cb = kc * 32 + lcolb;
            uint32_t af[4][4], bf[4][4];
            #pragma unroll
            for (int mt = 0; mt < 4; ++mt)
                ldm4(af[mt], aT + (wm * 64 + mt * 16 + lrow) * 144 + cb);
            #pragma unroll
            for (int jp = 0; jp < 4; ++jp)
                ldm4(bf[jp], bT + (wn * 64 + jp * 16 + lrow) * 144 + cb);
            #pragma unroll
            for (int jp = 0; jp < 4; ++jp)
                #pragma unroll
                for (int mt = 0; mt < 4; ++mt) {
                    mma16816(acc[mt][2 * jp],     af[mt], bf[jp][0], bf[jp][2]);
                    mma16816(acc[mt][2 * jp + 1], af[mt], bf[jp][1], bf[jp][3]);
                }
        }
    }

    // ---------------- epilogue ----------------
    if (QKV && uq >= 0) {
        // quarter-K partial: write fp32 128x128 tile to workspace
        float* wp = ws + (size_t)uq * (128 * 128);
        #pragma unroll
        for (int mt = 0; mt < 4; ++mt)
            #pragma unroll
            for (int rh = 0; rh < 2; ++rh) {
                const int row = wm * 64 + mt * 16 + g + rh * 8;
                #pragma unroll
                for (int nt = 0; nt < 8; ++nt) {
                    const int col = wn * 64 + nt * 8 + 2 * t;
                    *(float2*)(wp + row * 128 + col) =
                        make_float2(acc[mt][nt][rh * 2], acc[mt][nt][rh * 2 + 1]);
                }
            }
        return;
    }

    const int bxh = QKV ? n0 >> 7 : 0;   // head index for QKV
    #pragma unroll
    for (int mt = 0; mt < 4; ++mt) {
        #pragma unroll
        for (int rh = 0; rh < 2; ++rh) {
            const int m = m0 + wm * 64 + mt * 16 + g + rh * 8;
            const int tI = m & (TT - 1);
            const int b  = m >> 11;
            #pragma unroll
            for (int nt = 0; nt < 8; ++nt) {
                const int col = wn * 64 + nt * 8 + 2 * t;
                float v0 = acc[mt][nt][rh * 2 + 0];
                float v1 = acc[mt][nt][rh * 2 + 1];
                if (QKV) {
                    if (z < 2) {
                        const float* cT = (z == 0) ? cq : ck;
                        const float* sT = (z == 0) ? sq : sk;
                        const int d2 = col >> 1;
                        const float cs = cT[tI * 64 + d2];
                        const float sn = sT[tI * 64 + d2];
                        const float x0 = v0, x1 = v1;
                        v0 = x0 * cs - x1 * sn;
                        v1 = x1 * cs + x0 * sn;
                    }
                    const size_t bh = (size_t)b * HH + bxh;
                    if (z == 2) {
                        const size_t base = (bh * HD + col) * TT + tI;
                        vo[base]      = __float2half(v0);
                        vo[base + TT] = __float2half(v1);
                    } else {
                        const size_t off = (bh * TT + tI) * HD + col;
                        __half* op = (z == 0) ? qo : ko;
                        *(uint32_t*)(op + off) = packhf(__float2half(v0), __float2half(v1));
                    }
                } else {
                    float* op = fout + (size_t)m * DD + n0 + col;
                    *(float2*)op = make_float2(v0, v1);
                }
            }
        }
    }
}

// ---------------------------------------------------------------------------
// Fixup: sum 4 quarter-K partials per tail tile, V-transpose epilogue.
// 56 CTAs x 256 threads.  Deterministic (fixed summation order).
// ---------------------------------------------------------------------------
__global__ __launch_bounds__(256)
void fixup_kernel(const float* __restrict__ ws, __half* __restrict__ vo)
{
    const int tidx = QKV_FULL + blockIdx.x;       // z=2 guaranteed
    const int x = tidx & 15;                       // head
    const int y = (tidx >> 4) & 31;
    const int m0 = y * 128;
    const int tid = threadIdx.x;
    const int r = tid & 127;
    const int ch = tid >> 7;                       // 0/1
    const float* p0 = ws + (size_t)(blockIdx.x * 4 + 0) * (128 * 128);
    const float* p1 = p0 + 128 * 128;
    const float* p2 = p1 + 128 * 128;
    const float* p3 = p2 + 128 * 128;

    const int m = m0 + r;
    const int tI = m & (TT - 1);
    const int b  = m >> 11;
    const size_t bh = (size_t)b * HH + x;

    #pragma unroll
    for (int i = 0; i < 64; ++i) {
        const int col = i * 2 + ch;
        const int e = r * 128 + col;
        const float s = ((p0[e] + p1[e]) + p2[e]) + p3[e];
        vo[(bh * HD + col) * TT + tI] = __float2half(s);
    }
}

// ---------------------------------------------------------------------------
// Flash attention (unchanged from round 12: BR=64, 128 thr, 2 CTAs/SM)
// ---------------------------------------------------------------------------
#define AQ_STR 272
#define AV_STR 144
#define OFF_KV 17408
#define OFF_VH 17408
#define KV_BUF 35840
#define ATT_SMEM (OFF_KV + 2 * KV_BUF)   // 89088
#define ATHREADS 128

__device__ __forceinline__ void load_kv_chunk(
    uint32_t sb, int buf, int chunk, int bh,
    const __half* __restrict__ k_g, const __half* __restrict__ v_g, int tid)
{
    const uint32_t kb = sb + OFF_KV + buf * KV_BUF;
    const int s0 = chunk * 64;
    #pragma unroll
    for (int i = 0; i < 8; ++i) {
        const int idx = tid + ATHREADS * i;
        const int r = idx >> 4, c2 = idx & 15;
        const size_t gk = ((size_t)bh * TT + s0 + r) * HD + c2 * 8;
        cp_async16(kb + r * AQ_STR + c2 * 16, k_g + gk);
        const int rv = idx >> 3, cv = idx & 7;
        const size_t gv = ((size_t)bh * HD + rv) * TT + s0 + cv * 8;
        cp_async16(kb + OFF_VH + rv * AV_STR + cv * 16, v_g + gv);
    }
}

__global__ __launch_bounds__(ATHREADS, 2)
void attn_kernel(const __half* __restrict__ q_g, const __half* __restrict__ k_g,
                 const __half* __restrict__ v_g, __half* __restrict__ c_g)
{
    extern __shared__ __align__(128) uint8_t sm_raw[];
    const uint32_t sb = smem_to_u32(sm_raw);
    const int tid = threadIdx.x;
    const int wid = tid >> 5, lid = tid & 31;
    const int g = lid >> 2, t = lid & 3;
    const int bh = blockIdx.y;
    const int b = bh >> 4, h = bh & 15;
    const int q0 = blockIdx.x * 64;
    const int lrow = lid & 15;
    const int lcolb = (lid >> 4) * 16;

    const size_t qoff = ((size_t)bh * TT + q0) * HD;
    #pragma unroll
    for (int i = 0; i < 4; ++i) {
        const int idx = tid + ATHREADS * i;
        const int r = idx >> 3, c2 = idx & 7;
        const size_t gq = qoff + (size_t)r * HD + c2 * 16;
        cp_async16(sb + r * AQ_STR + c2 * 32,      q_g + gq);
        cp_async16(sb + r * AQ_STR + c2 * 32 + 16, q_g + gq + 8);
    }
    load_kv_chunk(sb, 0, 0, bh, k_g, v_g, tid);
    CP_ASYNC_COMMIT();
    load_kv_chunk(sb, 1, 1, bh, k_g, v_g, tid);
    CP_ASYNC_COMMIT();

    float O[16][4];
    #pragma unroll
    for (int nv = 0; nv < 16; ++nv)
        #pragma unroll
        for (int q = 0; q < 4; ++q) O[nv][q] = 0.0f;
    float mr0 = -1e30f, mr1 = -1e30f, lr0 = 0.0f, lr1 = 0.0f;

    for (int c = 0; c < 32; ++c) {
        CP_ASYNC_WAIT(1);
        __syncthreads();
        const uint32_t kb = sb + OFF_KV + (c & 1) * KV_BUF;

        float S[8][4];
        #pragma unroll
        for (int j = 0; j < 8; ++j)
            #pragma unroll
            for (int q = 0; q < 4; ++q) S[j][q] = 0.0f;

        #pragma unroll
        for (int ks = 0; ks < 8; ++ks) {
            const uint32_t cb = ks * 32 + lcolb;
            uint32_t qf[4], kf[4][4];
            ldm4(qf, sb + (wid * 16 + lrow) * AQ_STR + cb);
            #pragma unroll
            for (int jp = 0; jp < 4; ++jp)
                ldm4(kf[jp], kb + (jp * 16 + lrow) * AQ_STR + cb);
            #pragma unroll
            for (int jp = 0; jp < 4; ++jp) {
                mma16816(S[2 * jp],     qf, kf[jp][0], kf[jp][2]);
                mma16816(S[2 * jp + 1], qf, kf[jp][1], kf[jp][3]);
            }
        }

        float mx0 = -1e30f, mx1 = -1e30f;
        #pragma unroll
        for (int j = 0; j < 8; ++j) {
            #pragma unroll
            for (int q = 0; q < 4; ++q) S[j][q] *= SCALE;
            mx0 = fmaxf(mx0, fmaxf(S[j][0], S[j][1]));
            mx1 = fmaxf(mx1, fmaxf(S[j][2], S[j][3]));
        }
        mx0 = fmaxf(mx0, __shfl_xor_sync(0xffffffffu, mx0, 1));
        mx0 = fmaxf(mx0, __shfl_xor_sync(0xffffffffu, mx0, 2));
        mx1 = fmaxf(mx1, __shfl_xor_sync(0xffffffffu, mx1, 1));
        mx1 = fmaxf(mx1, __shfl_xor_sync(0xffffffffu, mx1, 2));
        const float mn0 = fmaxf(mr0, mx0), mn1 = fmaxf(mr1, mx1);
        const float cr0 = __expf(mr0 - mn0), cr1 = __expf(mr1 - mn1);
        mr0 = mn0; mr1 = mn1;
        float ls0 = 0.0f, ls1 = 0.0f;
        #pragma unroll
        for (int j = 0; j < 8; ++j) {
            S[j][0] = __expf(S[j][0] - mn0);
            S[j][1] = __expf(S[j][1] - mn0);
            S[j][2] = __expf(S[j][2] - mn1);
            S[j][3] = __expf(S[j][3] - mn1);
            ls0 += S[j][0] + S[j][1];
            ls1 += S[j][2] + S[j][3];
        }
        ls0 += __shfl_xor_sync(0xffffffffu, ls0, 1);
        ls0 += __shfl_xor_sync(0xffffffffu, ls0, 2);
        ls1 += __shfl_xor_sync(0xffffffffu, ls1, 1);
        ls1 += __shfl_xor_sync(0xffffffffu, ls1, 2);
        lr0 = lr0 * cr0 + ls0;
        lr1 = lr1 * cr1 + ls1;
        #pragma unroll
        for (int nv = 0; nv < 16; ++nv) {
            O[nv][0] *= cr0; O[nv][1] *= cr0;
            O[nv][2] *= cr1; O[nv][3] *= cr1;
        }

        uint32_t pf[4][4];
        #pragma unroll
        for (int kk = 0; kk < 4; ++kk) {
            pf[kk][0] = packhf(__float2half(S[2 * kk][0]),     __float2half(S[2 * kk][1]));
            pf[kk][1] = packhf(__float2half(S[2 * kk][2]),     __float2half(S[2 * kk][3]));
            pf[kk][2] = packhf(__float2half(S[2 * kk + 1][0]), __float2half(S[2 * kk + 1][1]));
            pf[kk][3] = packhf(__float2half(S[2 * kk + 1][2]), __float2half(S[2 * kk + 1][3]));
        }

        const uint32_t vb = kb + OFF_VH;
        #pragma unroll
        for (int kk = 0; kk < 4; ++kk) {
            const uint32_t cb = kk * 32 + lcolb;
            #pragma unroll
            for (int half = 0; half < 2; ++half) {
                uint32_t vf[4][4];
                #pragma unroll
                for (int u = 0; u < 4; ++u)
                    ldm4(vf[u], vb + ((half * 4 + u) * 16 + lrow) * AV_STR + cb);
                #pragma unroll
                for (int u = 0; u < 4; ++u) {
                    const int np = half * 4 + u;
                    mma16816(O[2 * np],     pf[kk], vf[u][0], vf[u][2]);
                    mma16816(O[2 * np + 1], pf[kk], vf[u][1], vf[u][3]);
                }
            }
        }

        __syncthreads();
        if (c + 2 < 32)
            load_kv_chunk(sb, c & 1, c + 2, bh, k_g, v_g, tid);
        CP_ASYNC_COMMIT();
    }

    const float inv0 = 1.0f / lr0, inv1 = 1.0f / lr1;
    const int t0 = q0 + wid * 16 + g;
    const int t1 = t0 + 8;
    #pragma unroll
    for (int nv = 0; nv < 16; ++nv) {
        const int d = h * HD + nv * 8 + 2 * t;
        const size_t o0 = ((size_t)b * TT + t0) * DD + d;
        const size_t o1 = ((size_t)b * TT + t1) * DD + d;
        *(uint32_t*)(c_g + o0) =
            packhf(__float2half(O[nv][0] * inv0), __float2half(O[nv][1] * inv0));
        *(uint32_t*)(c_g + o1) =
            packhf(__float2half(O[nv][2] * inv1), __float2half(O[nv][3] * inv1));
    }
}

// ---------------------------------------------------------------------------
extern "C" void kernel_launch(void* const* d_in, const int* in_sizes, int n_in,
                              void* d_out, int out_size)
{
    const float* hs  = (const float*)d_in[0];
    const float* enc = (const float*)d_in[1];
    const float* Wq  = (const float*)d_in[2];
    const float* Wk  = (const float*)d_in[3];
    const float* Wv  = (const float*)d_in[4];
    const float* Wo  = (const float*)d_in[5];
    const float* cq  = (const float*)d_in[6];
    const float* sq  = (const float*)d_in[7];
    const float* ck  = (const float*)d_in[8];
    const float* sk  = (const float*)d_in[9];

    __half *hs_c, *enc_c, *wq_c, *wk_c, *wv_c, *wo_c;
    __half *q_c, *k_c, *v_c, *c_c;
    float* ws_c;
    cudaGetSymbolAddress((void**)&hs_c,  g_hs);
    cudaGetSymbolAddress((void**)&enc_c, g_enc);
    cudaGetSymbolAddress((void**)&wq_c,  g_wq);
    cudaGetSymbolAddress((void**)&wk_c,  g_wk);
    cudaGetSymbolAddress((void**)&wv_c,  g_wv);
    cudaGetSymbolAddress((void**)&wo_c,  g_wo);
    cudaGetSymbolAddress((void**)&q_c, g_q);
    cudaGetSymbolAddress((void**)&k_c, g_k);
    cudaGetSymbolAddress((void**)&v_c, g_v);
    cudaGetSymbolAddress((void**)&c_c, g_c);
    cudaGetSymbolAddress((void**)&ws_c, g_ws);

    {
        const size_t nblocks = TOT_E / 32 / 256;   // 4096
        conv_all<<<(unsigned)nblocks, 256>>>(
            hs, enc, Wq, Wk, Wv, Wo, hs_c, enc_c, wq_c, wk_c, wv_c, wo_c);
    }

    cudaFuncSetAttribute(gemm_kernel<true>,
                         cudaFuncAttributeMaxDynamicSharedMemorySize, SMEM_GEMM);
    cudaFuncSetAttribute(gemm_kernel<false>,
                         cudaFuncAttributeMaxDynamicSharedMemorySize, SMEM_GEMM);
    cudaFuncSetAttribute(attn_kernel,
                         cudaFuncAttributeMaxDynamicSharedMemorySize, ATT_SMEM);

    // Q/K/V projections: 1480 full tiles + 224 quarter-K tail units
    gemm_kernel<true><<<QKV_FULL + TAIL_UNITS, GTHREADS, SMEM_GEMM>>>(
        hs_c, enc_c, wq_c, wk_c, wv_c,
        cq, sq, ck, sk, q_c, k_c, v_c, ws_c, nullptr);

    // Fixup: reduce tail partials into V
    fixup_kernel<<<QKV_TAIL, 256>>>(ws_c, v_c);

    // Attention (BR=64, 2 CTAs/SM)
    attn_kernel<<<dim3(TT / 64, BB * HH), ATHREADS, ATT_SMEM>>>(
        q_c, k_c, v_c, c_c);

    // Output projection (fp32 out)
    gemm_kernel<false><<<dim3(DD / 128, MM / 128, 1), GTHREADS, SMEM_GEMM>>>(
        c_c, nullptr, wo_c, nullptr, nullptr,
        nullptr, nullptr, nullptr, nullptr,
        nullptr, nullptr, nullptr, nullptr, (float*)d_out);
}

// round 14
// speedup vs baseline: 1.0198x; 1.0198x over previous
#include <cuda_runtime.h>
#include <cuda_fp16.h>
#include <cstdint>
#include <cstddef>
#include <math.h>

// ---------------------------------------------------------------------------
#define BB 2
#define HH 16
#define TT 2048
#define DD 2048
#define HD 128
#define KK 2048
#define MM 4096
#define SCALE 0.08838834764831845f
#define CH (BB * HH * TT * HD)

// ---------------------------------------------------------------------------
// Scratch (device globals; allocation is forbidden).  All single fp16.
// ---------------------------------------------------------------------------
__device__ __half g_hs[MM * KK];
__device__ __half g_enc[MM * KK];
__device__ __half g_wq[DD * KK];
__device__ __half g_wk[DD * KK];
__device__ __half g_wv[DD * KK];
__device__ __half g_wo[DD * KK];
__device__ __half g_q[CH];                  // [B,H,T,HD]  (pre-scaled by SCALE)
__device__ __half g_k[CH];                  // [B,H,S,HD]
__device__ __half g_v[CH];                  // [B,H,HD,S] transposed
__device__ __half g_c[MM * DD];             // ctx [B,T,D]

// ---------------------------------------------------------------------------
// Helpers (baseline sm_80 features only)
// ---------------------------------------------------------------------------
__device__ __forceinline__ uint32_t smem_to_u32(const void* p) {
    uint32_t a;
    asm("{ .reg .u64 t; cvta.to.shared.u64 t, %1; cvt.u32.u64 %0, t; }" : "=r"(a) : "l"(p));
    return a;
}
__device__ __forceinline__ void cp_async16(uint32_t dst, const void* src) {
    asm volatile("cp.async.cg.shared.global [%0], [%1], 16;" :: "r"(dst), "l"(src));
}
#define CP_ASYNC_COMMIT() asm volatile("cp.async.commit_group;" ::: "memory")
#define CP_ASYNC_WAIT(n)  asm volatile("cp.async.wait_group %0;" :: "n"(n) : "memory")

__device__ __forceinline__ void ldm4(uint32_t* r, uint32_t addr) {
    asm volatile("ldmatrix.sync.aligned.m8n8.x4.shared.b16 {%0,%1,%2,%3}, [%4];"
                 : "=r"(r[0]), "=r"(r[1]), "=r"(r[2]), "=r"(r[3]) : "r"(addr));
}
__device__ __forceinline__ void mma16816(float* c, const uint32_t* a, uint32_t b0, uint32_t b1) {
    asm volatile("mma.sync.aligned.m16n8k16.row.col.f32.f16.f16.f32 "
                 "{%0,%1,%2,%3}, {%4,%5,%6,%7}, {%8,%9}, {%0,%1,%2,%3};"
                 : "+f"(c[0]), "+f"(c[1]), "+f"(c[2]), "+f"(c[3])
                 : "r"(a[0]), "r"(a[1]), "r"(a[2]), "r"(a[3]), "r"(b0), "r"(b1));
}
__device__ __forceinline__ uint32_t packhf(__half a, __half b) {
    __half2 t(a, b);
    return *reinterpret_cast<uint32_t*>(&t);
}

// ---------------------------------------------------------------------------
// Fused fp32 -> fp16 convert, 32 elements/thread (8x LDG.128, 4x STG.128)
// ---------------------------------------------------------------------------
#define NAE ((size_t)MM * KK)
#define NWE ((size_t)DD * KK)
#define TOT_E (2 * NAE + 4 * NWE)            // 32M elements

__global__ __launch_bounds__(256)
void conv_all(const float* __restrict__ hs, const float* __restrict__ enc,
              const float* __restrict__ wq, const float* __restrict__ wk,
              const float* __restrict__ wv, const float* __restrict__ wo,
              __half* __restrict__ hs_o, __half* __restrict__ enc_o,
              __half* __restrict__ wq_o, __half* __restrict__ wk_o,
              __half* __restrict__ wv_o, __half* __restrict__ wo_o)
{
    size_t e = ((size_t)blockIdx.x * 256 + threadIdx.x) * 32;
    if (e >= TOT_E) return;
    const float* src; __half* dst; size_t base;
    if      (e < NAE)            { src = hs;  dst = hs_o;  base = 0; }
    else if (e < 2 * NAE)        { src = enc; dst = enc_o; base = NAE; }
    else if (e < 2 * NAE + NWE)  { src = wq;  dst = wq_o;  base = 2 * NAE; }
    else if (e < 2 * NAE + 2 * NWE) { src = wk; dst = wk_o; base = 2 * NAE + NWE; }
    else if (e < 2 * NAE + 3 * NWE) { src = wv; dst = wv_o; base = 2 * NAE + 2 * NWE; }
    else                         { src = wo;  dst = wo_o;  base = 2 * NAE + 3 * NWE; }
    const size_t j = e - base;
    const float4* s4 = (const float4*)src + (j >> 2);
    uint4* d4 = (uint4*)dst + (j >> 3);
    #pragma unroll
    for (int v = 0; v < 4; ++v) {
        float4 a = s4[2 * v];
        float4 b = s4[2 * v + 1];
        uint4 o;
        o.x = packhf(__float2half(a.x), __float2half(a.y));
        o.y = packhf(__float2half(a.z), __float2half(a.w));
        o.z = packhf(__float2half(b.x), __float2half(b.y));
        o.w = packhf(__float2half(b.z), __float2half(b.w));
        d4[v] = o;
    }
}

// ---------------------------------------------------------------------------
// 1-pass fp16 GEMM (round-12 champion: 128x128 CTA tile, BK=64,
// 4 warps 64x64, 3-stage ring, 2 CTAs/SM — 91% of HMMA ceiling).
// Round-13 change: z==0 (Q) epilogue folds SCALE after RoPE.
// ---------------------------------------------------------------------------
#define TILE_B 18432                   // 128 rows * 144B
#define STAGE_B (2 * TILE_B)
#define SMEM_GEMM (3 * STAGE_B)        // 110592 -> 2 CTAs/SM
#define NSTAGES (KK / 64)              // 32
#define GTHREADS 128

__device__ __forceinline__ void load_stage_g(
    uint32_t sbuf, int s, int m0, int n0,
    const __half* __restrict__ A, const __half* __restrict__ W, int tid)
{
    const int k0 = s * 64;
    #pragma unroll
    for (int q = 0; q < 8; ++q) {
        const int id = tid + GTHREADS * q;      // 0..1023
        const int r = id >> 3, c = id & 7;
        const uint32_t doff = r * 144 + c * 16;
        const size_t gA = (size_t)(m0 + r) * KK + k0 + c * 8;
        const size_t gW = (size_t)(n0 + r) * KK + k0 + c * 8;
        cp_async16(sbuf + doff,          A + gA);
        cp_async16(sbuf + TILE_B + doff, W + gW);
    }
}

template<bool QKV>
__global__ __launch_bounds__(GTHREADS, 2)
void gemm_kernel(const __half* __restrict__ a0, const __half* __restrict__ a1,
                 const __half* __restrict__ w0, const __half* __restrict__ w1,
                 const __half* __restrict__ w2,
                 const float* __restrict__ cq, const float* __restrict__ sq,
                 const float* __restrict__ ck, const float* __restrict__ sk,
                 __half* __restrict__ qo, __half* __restrict__ ko,
                 __half* __restrict__ vo,
                 float* __restrict__ fout)
{
    extern __shared__ __align__(128) uint8_t smem_raw[];
    const uint32_t sbase = smem_to_u32(smem_raw);
    const int tid = threadIdx.x;
    const int m0 = blockIdx.y * 128;
    const int n0 = blockIdx.x * 128;
    const int z  = QKV ? blockIdx.z : 0;

    const __half *A, *W;
    if (QKV) {
        A = (z == 0) ? a0 : a1;
        W = (z == 0) ? w0 : (z == 1) ? w1 : w2;
    } else {
        A = a0; W = w0;
    }

    const int wid = tid >> 5, lid = tid & 31;
    const int wm = wid >> 1, wn = wid & 1;
    const int g = lid >> 2, t = lid & 3;
    const int lrow = lid & 15;
    const int lcolb = (lid >> 4) * 16;

    float acc[4][8][4];
    #pragma unroll
    for (int mt = 0; mt < 4; ++mt)
        #pragma unroll
        for (int nt = 0; nt < 8; ++nt)
            #pragma unroll
            for (int q = 0; q < 4; ++q) acc[mt][nt][q] = 0.0f;

    load_stage_g(sbase, 0, m0, n0, A, W, tid); CP_ASYNC_COMMIT();
    load_stage_g(sbase + STAGE_B, 1, m0, n0, A, W, tid); CP_ASYNC_COMMIT();

    for (int s = 0; s < NSTAGES; ++s) {
        CP_ASYNC_WAIT(1);
        __syncthreads();
        if (s + 2 < NSTAGES) {
            int bslot = s + 2 - ((s + 2) / 3) * 3;
            load_stage_g(sbase + bslot * STAGE_B, s + 2, m0, n0, A, W, tid);
        }
        CP_ASYNC_COMMIT();

        const uint32_t buf = sbase + (s % 3) * STAGE_B;
        const uint32_t aT = buf, bT = buf + TILE_B;

        #pragma unroll
        for (int kc = 0; kc < 4; ++kc) {
            const uint32_t cb = kc * 32 + lcolb;
            uint32_t af[4][4], bf[4][4];
            #pragma unroll
            for (int mt = 0; mt < 4; ++mt)
                ldm4(af[mt], aT + (wm * 64 + mt * 16 + lrow) * 144 + cb);
            #pragma unroll
            for (int jp = 0; jp < 4; ++jp)
                ldm4(bf[jp], bT + (wn * 64 + jp * 16 + lrow) * 144 + cb);
            #pragma unroll
            for (int jp = 0; jp < 4; ++jp)
                #pragma unroll
                for (int mt = 0; mt < 4; ++mt) {
                    mma16816(acc[mt][2 * jp],     af[mt], bf[jp][0], bf[jp][2]);
                    mma16816(acc[mt][2 * jp + 1], af[mt], bf[jp][1], bf[jp][3]);
                }
        }
    }

    // ---------------- epilogue ----------------
    #pragma unroll
    for (int mt = 0; mt < 4; ++mt) {
        #pragma unroll
        for (int rh = 0; rh < 2; ++rh) {
            const int m = m0 + wm * 64 + mt * 16 + g + rh * 8;
            const int tI = m & (TT - 1);
            const int b  = m >> 11;
            #pragma unroll
            for (int nt = 0; nt < 8; ++nt) {
                const int col = wn * 64 + nt * 8 + 2 * t;
                float v0 = acc[mt][nt][rh * 2 + 0];
                float v1 = acc[mt][nt][rh * 2 + 1];
                if (QKV) {
                    if (z < 2) {
                        const float* cT = (z == 0) ? cq : ck;
                        const float* sT = (z == 0) ? sq : sk;
                        const int d2 = col >> 1;
                        const float cs = cT[tI * 64 + d2];
                        const float sn = sT[tI * 64 + d2];
                        const float x0 = v0, x1 = v1;
                        v0 = x0 * cs - x1 * sn;
                        v1 = x1 * cs + x0 * sn;
                        if (z == 0) { v0 *= SCALE; v1 *= SCALE; }  // fold softmax scale into Q
                    }
                    const int hhead = blockIdx.x;
                    const size_t bh = (size_t)b * HH + hhead;
                    if (z == 2) {
                        const size_t base = (bh * HD + col) * TT + tI;
                        vo[base]      = __float2half(v0);
                        vo[base + TT] = __float2half(v1);
                    } else {
                        const size_t off = (bh * TT + tI) * HD + col;
                        __half* op = (z == 0) ? qo : ko;
                        *(uint32_t*)(op + off) = packhf(__float2half(v0), __float2half(v1));
                    }
                } else {
                    float* op = fout + (size_t)m * DD + n0 + col;
                    *(float2*)op = make_float2(v0, v1);
                }
            }
        }
    }
}

// ---------------------------------------------------------------------------
// Flash attention: BR=64, 128 threads (4 warps x 16 rows), 2 CTAs/SM.
// Q is pre-scaled by SCALE, so scores come out of QK^T ready for softmax.
// ---------------------------------------------------------------------------
#define AQ_STR 272
#define AV_STR 144
#define OFF_KV 17408                 // 64*272 (Q)
#define OFF_VH 17408                 // within buf: after K
#define KV_BUF 35840                 // 17408 + 18432
#define ATT_SMEM (OFF_KV + 2 * KV_BUF)   // 89088 -> 2 CTAs/SM
#define ATHREADS 128

__device__ __forceinline__ void load_kv_chunk(
    uint32_t sb, int buf, int chunk, int bh,
    const __half* __restrict__ k_g, const __half* __restrict__ v_g, int tid)
{
    const uint32_t kb = sb + OFF_KV + buf * KV_BUF;
    const int s0 = chunk * 64;
    #pragma unroll
    for (int i = 0; i < 8; ++i) {
        const int idx = tid + ATHREADS * i;     // 0..1023
        const int r = idx >> 4, c2 = idx & 15;  // K: 64 rows x 16 chunks
        const size_t gk = ((size_t)bh * TT + s0 + r) * HD + c2 * 8;
        cp_async16(kb + r * AQ_STR + c2 * 16, k_g + gk);
        const int rv = idx >> 3, cv = idx & 7;  // Vt: 128 rows x 8 chunks
        const size_t gv = ((size_t)bh * HD + rv) * TT + s0 + cv * 8;
        cp_async16(kb + OFF_VH + rv * AV_STR + cv * 16, v_g + gv);
    }
}

__global__ __launch_bounds__(ATHREADS, 2)
void attn_kernel(const __half* __restrict__ q_g, const __half* __restrict__ k_g,
                 const __half* __restrict__ v_g, __half* __restrict__ c_g)
{
    extern __shared__ __align__(128) uint8_t sm_raw[];
    const uint32_t sb = smem_to_u32(sm_raw);
    const int tid = threadIdx.x;
    const int wid = tid >> 5, lid = tid & 31;
    const int g = lid >> 2, t = lid & 3;
    const int bh = blockIdx.y;
    const int b = bh >> 4, h = bh & 15;
    const int q0 = blockIdx.x * 64;
    const int lrow = lid & 15;
    const int lcolb = (lid >> 4) * 16;

    const size_t qoff = ((size_t)bh * TT + q0) * HD;
    #pragma unroll
    for (int i = 0; i < 4; ++i) {
        const int idx = tid + ATHREADS * i;     // 0..511
        const int r = idx >> 3, c2 = idx & 7;
        const size_t gq = qoff + (size_t)r * HD + c2 * 16;
        cp_async16(sb + r * AQ_STR + c2 * 32,      q_g + gq);
        cp_async16(sb + r * AQ_STR + c2 * 32 + 16, q_g + gq + 8);
    }
    load_kv_chunk(sb, 0, 0, bh, k_g, v_g, tid);
    CP_ASYNC_COMMIT();
    load_kv_chunk(sb, 1, 1, bh, k_g, v_g, tid);
    CP_ASYNC_COMMIT();

    float O[16][4];
    #pragma unroll
    for (int nv = 0; nv < 16; ++nv)
        #pragma unroll
        for (int q = 0; q < 4; ++q) O[nv][q] = 0.0f;
    float mr0 = -1e30f, mr1 = -1e30f, lr0 = 0.0f, lr1 = 0.0f;

    for (int c = 0; c < 32; ++c) {
        CP_ASYNC_WAIT(1);
        __syncthreads();
        const uint32_t kb = sb + OFF_KV + (c & 1) * KV_BUF;

        // ---- S = Q K^T (Q pre-scaled; scores softmax-ready) ----
        float S[8][4];
        #pragma unroll
        for (int j = 0; j < 8; ++j)
            #pragma unroll
            for (int q = 0; q < 4; ++q) S[j][q] = 0.0f;

        #pragma unroll
        for (int ks = 0; ks < 8; ++ks) {
            const uint32_t cb = ks * 32 + lcolb;
            uint32_t qf[4], kf[4][4];
            ldm4(qf, sb + (wid * 16 + lrow) * AQ_STR + cb);
            #pragma unroll
            for (int jp = 0; jp < 4; ++jp)
                ldm4(kf[jp], kb + (jp * 16 + lrow) * AQ_STR + cb);
            #pragma unroll
            for (int jp = 0; jp < 4; ++jp) {
                mma16816(S[2 * jp],     qf, kf[jp][0], kf[jp][2]);
                mma16816(S[2 * jp + 1], qf, kf[jp][1], kf[jp][3]);
            }
        }

        // ---- online softmax (fp32; no scale pass needed) ----
        float mx0 = -1e30f, mx1 = -1e30f;
        #pragma unroll
        for (int j = 0; j < 8; ++j) {
            mx0 = fmaxf(mx0, fmaxf(S[j][0], S[j][1]));
            mx1 = fmaxf(mx1, fmaxf(S[j][2], S[j][3]));
        }
        mx0 = fmaxf(mx0, __shfl_xor_sync(0xffffffffu, mx0, 1));
        mx0 = fmaxf(mx0, __shfl_xor_sync(0xffffffffu, mx0, 2));
        mx1 = fmaxf(mx1, __shfl_xor_sync(0xffffffffu, mx1, 1));
        mx1 = fmaxf(mx1, __shfl_xor_sync(0xffffffffu, mx1, 2));
        const float mn0 = fmaxf(mr0, mx0), mn1 = fmaxf(mr1, mx1);
        const float cr0 = __expf(mr0 - mn0), cr1 = __expf(mr1 - mn1);
        mr0 = mn0; mr1 = mn1;
        float ls0 = 0.0f, ls1 = 0.0f;
        #pragma unroll
        for (int j = 0; j < 8; ++j) {
            S[j][0] = __expf(S[j][0] - mn0);
            S[j][1] = __expf(S[j][1] - mn0);
            S[j][2] = __expf(S[j][2] - mn1);
            S[j][3] = __expf(S[j][3] - mn1);
            ls0 += S[j][0] + S[j][1];
            ls1 += S[j][2] + S[j][3];
        }
        ls0 += __shfl_xor_sync(0xffffffffu, ls0, 1);
        ls0 += __shfl_xor_sync(0xffffffffu, ls0, 2);
        ls1 += __shfl_xor_sync(0xffffffffu, ls1, 1);
        ls1 += __shfl_xor_sync(0xffffffffu, ls1, 2);
        lr0 = lr0 * cr0 + ls0;
        lr1 = lr1 * cr1 + ls1;
        #pragma unroll
        for (int nv = 0; nv < 16; ++nv) {
            O[nv][0] *= cr0; O[nv][1] *= cr0;
            O[nv][2] *= cr1; O[nv][3] *= cr1;
        }

        // ---- P fragments (single fp16) ----
        uint32_t pf[4][4];
        #pragma unroll
        for (int kk = 0; kk < 4; ++kk) {
            pf[kk][0] = packhf(__float2half(S[2 * kk][0]),     __float2half(S[2 * kk][1]));
            pf[kk][1] = packhf(__float2half(S[2 * kk][2]),     __float2half(S[2 * kk][3]));
            pf[kk][2] = packhf(__float2half(S[2 * kk + 1][0]), __float2half(S[2 * kk + 1][1]));
            pf[kk][3] = packhf(__float2half(S[2 * kk + 1][2]), __float2half(S[2 * kk + 1][3]));
        }

        // ---- O += P V (1-pass) ----
        const uint32_t vb = kb + OFF_VH;
        #pragma unroll
        for (int kk = 0; kk < 4; ++kk) {
            const uint32_t cb = kk * 32 + lcolb;
            #pragma unroll
            for (int half = 0; half < 2; ++half) {
                uint32_t vf[4][4];
                #pragma unroll
                for (int u = 0; u < 4; ++u)
                    ldm4(vf[u], vb + ((half * 4 + u) * 16 + lrow) * AV_STR + cb);
                #pragma unroll
                for (int u = 0; u < 4; ++u) {
                    const int np = half * 4 + u;
                    mma16816(O[2 * np],     pf[kk], vf[u][0], vf[u][2]);
                    mma16816(O[2 * np + 1], pf[kk], vf[u][1], vf[u][3]);
                }
            }
        }

        __syncthreads();
        if (c + 2 < 32)
            load_kv_chunk(sb, c & 1, c + 2, bh, k_g, v_g, tid);
        CP_ASYNC_COMMIT();
    }

    // ---- epilogue: ctx single fp16 ----
    const float inv0 = 1.0f / lr0, inv1 = 1.0f / lr1;
    const int t0 = q0 + wid * 16 + g;
    const int t1 = t0 + 8;
    #pragma unroll
    for (int nv = 0; nv < 16; ++nv) {
        const int d = h * HD + nv * 8 + 2 * t;
        const size_t o0 = ((size_t)b * TT + t0) * DD + d;
        const size_t o1 = ((size_t)b * TT + t1) * DD + d;
        *(uint32_t*)(c_g + o0) =
            packhf(__float2half(O[nv][0] * inv0), __float2half(O[nv][1] * inv0));
        *(uint32_t*)(c_g + o1) =
            packhf(__float2half(O[nv][2] * inv1), __float2half(O[nv][3] * inv1));
    }
}

// ---------------------------------------------------------------------------
extern "C" void kernel_launch(void* const* d_in, const int* in_sizes, int n_in,
                              void* d_out, int out_size)
{
    const float* hs  = (const float*)d_in[0];
    const float* enc = (const float*)d_in[1];
    const float* Wq  = (const float*)d_in[2];
    const float* Wk  = (const float*)d_in[3];
    const float* Wv  = (const float*)d_in[4];
    const float* Wo  = (const float*)d_in[5];
    const float* cq  = (const float*)d_in[6];
    const float* sq  = (const float*)d_in[7];
    const float* ck  = (const float*)d_in[8];
    const float* sk  = (const float*)d_in[9];

    __half *hs_c, *enc_c, *wq_c, *wk_c, *wv_c, *wo_c;
    __half *q_c, *k_c, *v_c, *c_c;
    cudaGetSymbolAddress((void**)&hs_c,  g_hs);
    cudaGetSymbolAddress((void**)&enc_c, g_enc);
    cudaGetSymbolAddress((void**)&wq_c,  g_wq);
    cudaGetSymbolAddress((void**)&wk_c,  g_wk);
    cudaGetSymbolAddress((void**)&wv_c,  g_wv);
    cudaGetSymbolAddress((void**)&wo_c,  g_wo);
    cudaGetSymbolAddress((void**)&q_c, g_q);
    cudaGetSymbolAddress((void**)&k_c, g_k);
    cudaGetSymbolAddress((void**)&v_c, g_v);
    cudaGetSymbolAddress((void**)&c_c, g_c);

    {
        const size_t nblocks = TOT_E / 32 / 256;   // 4096
        conv_all<<<(unsigned)nblocks, 256>>>(
            hs, enc, Wq, Wk, Wv, Wo, hs_c, enc_c, wq_c, wk_c, wv_c, wo_c);
    }

    cudaFuncSetAttribute(gemm_kernel<true>,
                         cudaFuncAttributeMaxDynamicSharedMemorySize, SMEM_GEMM);
    cudaFuncSetAttribute(gemm_kernel<false>,
                         cudaFuncAttributeMaxDynamicSharedMemorySize, SMEM_GEMM);
    cudaFuncSetAttribute(attn_kernel,
                         cudaFuncAttributeMaxDynamicSharedMemorySize, ATT_SMEM);

    // Q/K/V projections (+RoPE +SCALE-fold, +head split, +V transpose)
    gemm_kernel<true><<<dim3(DD / 128, MM / 128, 3), GTHREADS, SMEM_GEMM>>>(
        hs_c, enc_c, wq_c, wk_c, wv_c,
        cq, sq, ck, sk, q_c, k_c, v_c, nullptr);

    // Attention (BR=64, 2 CTAs/SM)
    attn_kernel<<<dim3(TT / 64, BB * HH), ATHREADS, ATT_SMEM>>>(
        q_c, k_c, v_c, c_c);

    // Output projection (fp32 out)
    gemm_kernel<false><<<dim3(DD / 128, MM / 128, 1), GTHREADS, SMEM_GEMM>>>(
        c_c, nullptr, wo_c, nullptr, nullptr,
        nullptr, nullptr, nullptr, nullptr,
        nullptr, nullptr, nullptr, (float*)d_out);
}

// round 15
// speedup vs baseline: 1.0383x; 1.0182x over previous
#include <cuda_runtime.h>
#include <cuda_fp16.h>
#include <cstdint>
#include <cstddef>
#include <math.h>

// ---------------------------------------------------------------------------
#define BB 2
#define HH 16
#define TT 2048
#define DD 2048
#define HD 128
#define KK 2048
#define MM 4096
#define SCALE 0.08838834764831845f
#define LOG2E 1.4426950408889634f
#define QSCALE (SCALE * LOG2E)          // folded into Q: scores in log2 domain
#define CH (BB * HH * TT * HD)

// ---------------------------------------------------------------------------
// Scratch (device globals; allocation is forbidden).  All single fp16.
// ---------------------------------------------------------------------------
__device__ __half g_hs[MM * KK];
__device__ __half g_enc[MM * KK];
__device__ __half g_wq[DD * KK];
__device__ __half g_wk[DD * KK];
__device__ __half g_wv[DD * KK];
__device__ __half g_wo[DD * KK];
__device__ __half g_q[CH];                  // [B,H,T,HD]  (pre-scaled by QSCALE)
__device__ __half g_k[CH];                  // [B,H,S,HD]
__device__ __half g_v[CH];                  // [B,H,HD,S] transposed
__device__ __half g_c[MM * DD];             // ctx [B,T,D]

// ---------------------------------------------------------------------------
// Helpers (baseline sm_80 features only)
// ---------------------------------------------------------------------------
__device__ __forceinline__ uint32_t smem_to_u32(const void* p) {
    uint32_t a;
    asm("{ .reg .u64 t; cvta.to.shared.u64 t, %1; cvt.u32.u64 %0, t; }" : "=r"(a) : "l"(p));
    return a;
}
__device__ __forceinline__ void cp_async16(uint32_t dst, const void* src) {
    asm volatile("cp.async.cg.shared.global [%0], [%1], 16;" :: "r"(dst), "l"(src));
}
#define CP_ASYNC_COMMIT() asm volatile("cp.async.commit_group;" ::: "memory")
#define CP_ASYNC_WAIT(n)  asm volatile("cp.async.wait_group %0;" :: "n"(n) : "memory")

__device__ __forceinline__ void ldm4(uint32_t* r, uint32_t addr) {
    asm volatile("ldmatrix.sync.aligned.m8n8.x4.shared.b16 {%0,%1,%2,%3}, [%4];"
                 : "=r"(r[0]), "=r"(r[1]), "=r"(r[2]), "=r"(r[3]) : "r"(addr));
}
__device__ __forceinline__ void mma16816(float* c, const uint32_t* a, uint32_t b0, uint32_t b1) {
    asm volatile("mma.sync.aligned.m16n8k16.row.col.f32.f16.f16.f32 "
                 "{%0,%1,%2,%3}, {%4,%5,%6,%7}, {%8,%9}, {%0,%1,%2,%3};"
                 : "+f"(c[0]), "+f"(c[1]), "+f"(c[2]), "+f"(c[3])
                 : "r"(a[0]), "r"(a[1]), "r"(a[2]), "r"(a[3]), "r"(b0), "r"(b1));
}
__device__ __forceinline__ uint32_t packhf(__half a, __half b) {
    __half2 t(a, b);
    return *reinterpret_cast<uint32_t*>(&t);
}
__device__ __forceinline__ float ex2(float x) {
    float y;
    asm("ex2.approx.f32 %0, %1;" : "=f"(y) : "f"(x));
    return y;
}

// ---------------------------------------------------------------------------
// Fused fp32 -> fp16 convert, COALESCED (round-14 fix: lane-contiguous
// float4 loads; the old layout strided lanes by 128B and wasted 7/8 of
// each L1 wavefront).  Block = 8192 elements (divides all boundaries).
// ---------------------------------------------------------------------------
#define NAE ((size_t)MM * KK)
#define NWE ((size_t)DD * KK)
#define TOT_E (2 * NAE + 4 * NWE)            // 32M elements

__global__ __launch_bounds__(256)
void conv_all(const float* __restrict__ hs, const float* __restrict__ enc,
              const float* __restrict__ wq, const float* __restrict__ wk,
              const float* __restrict__ wv, const float* __restrict__ wo,
              __half* __restrict__ hs_o, __half* __restrict__ enc_o,
              __half* __restrict__ wq_o, __half* __restrict__ wk_o,
              __half* __restrict__ wv_o, __half* __restrict__ wo_o)
{
    const size_t e0 = (size_t)blockIdx.x * 8192;   // block's element base
    const float* src; __half* dst; size_t base;
    if      (e0 < NAE)            { src = hs;  dst = hs_o;  base = 0; }
    else if (e0 < 2 * NAE)        { src = enc; dst = enc_o; base = NAE; }
    else if (e0 < 2 * NAE + NWE)  { src = wq;  dst = wq_o;  base = 2 * NAE; }
    else if (e0 < 2 * NAE + 2 * NWE) { src = wk; dst = wk_o; base = 2 * NAE + NWE; }
    else if (e0 < 2 * NAE + 3 * NWE) { src = wv; dst = wv_o; base = 2 * NAE + 2 * NWE; }
    else                          { src = wo;  dst = wo_o;  base = 2 * NAE + 3 * NWE; }
    const size_t j4 = (e0 - base) >> 2;            // float4 offset
    const float4* s4 = (const float4*)src + j4;
    uint2* d2 = (uint2*)dst + j4;                   // one uint2 per float4
    const int tid = threadIdx.x;
    #pragma unroll
    for (int v = 0; v < 8; ++v) {
        const int idx = v * 256 + tid;              // coalesced
        float4 a = s4[idx];
        uint2 o;
        o.x = packhf(__float2half(a.x), __float2half(a.y));
        o.y = packhf(__float2half(a.z), __float2half(a.w));
        d2[idx] = o;
    }
}

// ---------------------------------------------------------------------------
// 1-pass fp16 GEMM (round-12 champion: 128x128 CTA tile, BK=64,
// 4 warps 64x64, 3-stage ring, 2 CTAs/SM — 91% of HMMA ceiling).
// z==0 (Q) epilogue folds QSCALE (= softmax scale * log2e) after RoPE.
// ---------------------------------------------------------------------------
#define TILE_B 18432                   // 128 rows * 144B
#define STAGE_B (2 * TILE_B)
#define SMEM_GEMM (3 * STAGE_B)        // 110592 -> 2 CTAs/SM
#define NSTAGES (KK / 64)              // 32
#define GTHREADS 128

__device__ __forceinline__ void load_stage_g(
    uint32_t sbuf, int s, int m0, int n0,
    const __half* __restrict__ A, const __half* __restrict__ W, int tid)
{
    const int k0 = s * 64;
    #pragma unroll
    for (int q = 0; q < 8; ++q) {
        const int id = tid + GTHREADS * q;      // 0..1023
        const int r = id >> 3, c = id & 7;
        const uint32_t doff = r * 144 + c * 16;
        const size_t gA = (size_t)(m0 + r) * KK + k0 + c * 8;
        const size_t gW = (size_t)(n0 + r) * KK + k0 + c * 8;
        cp_async16(sbuf + doff,          A + gA);
        cp_async16(sbuf + TILE_B + doff, W + gW);
    }
}

template<bool QKV>
__global__ __launch_bounds__(GTHREADS, 2)
void gemm_kernel(const __half* __restrict__ a0, const __half* __restrict__ a1,
                 const __half* __restrict__ w0, const __half* __restrict__ w1,
                 const __half* __restrict__ w2,
                 const float* __restrict__ cq, const float* __restrict__ sq,
                 const float* __restrict__ ck, const float* __restrict__ sk,
                 __half* __restrict__ qo, __half* __restrict__ ko,
                 __half* __restrict__ vo,
                 float* __restrict__ fout)
{
    extern __shared__ __align__(128) uint8_t smem_raw[];
    const uint32_t sbase = smem_to_u32(smem_raw);
    const int tid = threadIdx.x;
    const int m0 = blockIdx.y * 128;
    const int n0 = blockIdx.x * 128;
    const int z  = QKV ? blockIdx.z : 0;

    const __half *A, *W;
    if (QKV) {
        A = (z == 0) ? a0 : a1;
        W = (z == 0) ? w0 : (z == 1) ? w1 : w2;
    } else {
        A = a0; W = w0;
    }

    const int wid = tid >> 5, lid = tid & 31;
    const int wm = wid >> 1, wn = wid & 1;
    const int g = lid >> 2, t = lid & 3;
    const int lrow = lid & 15;
    const int lcolb = (lid >> 4) * 16;

    float acc[4][8][4];
    #pragma unroll
    for (int mt = 0; mt < 4; ++mt)
        #pragma unroll
        for (int nt = 0; nt < 8; ++nt)
            #pragma unroll
            for (int q = 0; q < 4; ++q) acc[mt][nt][q] = 0.0f;

    load_stage_g(sbase, 0, m0, n0, A, W, tid); CP_ASYNC_COMMIT();
    load_stage_g(sbase + STAGE_B, 1, m0, n0, A, W, tid); CP_ASYNC_COMMIT();

    for (int s = 0; s < NSTAGES; ++s) {
        CP_ASYNC_WAIT(1);
        __syncthreads();
        if (s + 2 < NSTAGES) {
            int bslot = s + 2 - ((s + 2) / 3) * 3;
            load_stage_g(sbase + bslot * STAGE_B, s + 2, m0, n0, A, W, tid);
        }
        CP_ASYNC_COMMIT();

        const uint32_t buf = sbase + (s % 3) * STAGE_B;
        const uint32_t aT = buf, bT = buf + TILE_B;

        #pragma unroll
        for (int kc = 0; kc < 4; ++kc) {
            const uint32_t cb = kc * 32 + lcolb;
            uint32_t af[4][4], bf[4][4];
            #pragma unroll
            for (int mt = 0; mt < 4; ++mt)
                ldm4(af[mt], aT + (wm * 64 + mt * 16 + lrow) * 144 + cb);
            #pragma unroll
            for (int jp = 0; jp < 4; ++jp)
                ldm4(bf[jp], bT + (wn * 64 + jp * 16 + lrow) * 144 + cb);
            #pragma unroll
            for (int jp = 0; jp < 4; ++jp)
                #pragma unroll
                for (int mt = 0; mt < 4; ++mt) {
                    mma16816(acc[mt][2 * jp],     af[mt], bf[jp][0], bf[jp][2]);
                    mma16816(acc[mt][2 * jp + 1], af[mt], bf[jp][1], bf[jp][3]);
                }
        }
    }

    // ---------------- epilogue ----------------
    #pragma unroll
    for (int mt = 0; mt < 4; ++mt) {
        #pragma unroll
        for (int rh = 0; rh < 2; ++rh) {
            const int m = m0 + wm * 64 + mt * 16 + g + rh * 8;
            const int tI = m & (TT - 1);
            const int b  = m >> 11;
            #pragma unroll
            for (int nt = 0; nt < 8; ++nt) {
                const int col = wn * 64 + nt * 8 + 2 * t;
                float v0 = acc[mt][nt][rh * 2 + 0];
                float v1 = acc[mt][nt][rh * 2 + 1];
                if (QKV) {
                    if (z < 2) {
                        const float* cT = (z == 0) ? cq : ck;
                        const float* sT = (z == 0) ? sq : sk;
                        const int d2 = col >> 1;
                        const float cs = cT[tI * 64 + d2];
                        const float sn = sT[tI * 64 + d2];
                        const float x0 = v0, x1 = v1;
                        v0 = x0 * cs - x1 * sn;
                        v1 = x1 * cs + x0 * sn;
                        if (z == 0) { v0 *= QSCALE; v1 *= QSCALE; }  // scale + log2e fold
                    }
                    const int hhead = blockIdx.x;
                    const size_t bh = (size_t)b * HH + hhead;
                    if (z == 2) {
                        const size_t base = (bh * HD + col) * TT + tI;
                        vo[base]      = __float2half(v0);
                        vo[base + TT] = __float2half(v1);
                    } else {
                        const size_t off = (bh * TT + tI) * HD + col;
                        __half* op = (z == 0) ? qo : ko;
                        *(uint32_t*)(op + off) = packhf(__float2half(v0), __float2half(v1));
                    }
                } else {
                    float* op = fout + (size_t)m * DD + n0 + col;
                    *(float2*)op = make_float2(v0, v1);
                }
            }
        }
    }
}

// ---------------------------------------------------------------------------
// Flash attention: BR=64, 128 threads, 2 CTAs/SM.  Scores arrive in the
// log2 domain (Q pre-scaled by SCALE*log2e); softmax uses ex2.approx.
// ---------------------------------------------------------------------------
#define AQ_STR 272
#define AV_STR 144
#define OFF_KV 17408                 // 64*272 (Q)
#define OFF_VH 17408                 // within buf: after K
#define KV_BUF 35840                 // 17408 + 18432
#define ATT_SMEM (OFF_KV + 2 * KV_BUF)   // 89088 -> 2 CTAs/SM
#define ATHREADS 128

__device__ __forceinline__ void load_kv_chunk(
    uint32_t sb, int buf, int chunk, int bh,
    const __half* __restrict__ k_g, const __half* __restrict__ v_g, int tid)
{
    const uint32_t kb = sb + OFF_KV + buf * KV_BUF;
    const int s0 = chunk * 64;
    #pragma unroll
    for (int i = 0; i < 8; ++i) {
        const int idx = tid + ATHREADS * i;     // 0..1023
        const int r = idx >> 4, c2 = idx & 15;  // K: 64 rows x 16 chunks
        const size_t gk = ((size_t)bh * TT + s0 + r) * HD + c2 * 8;
        cp_async16(kb + r * AQ_STR + c2 * 16, k_g + gk);
        const int rv = idx >> 3, cv = idx & 7;  // Vt: 128 rows x 8 chunks
        const size_t gv = ((size_t)bh * HD + rv) * TT + s0 + cv * 8;
        cp_async16(kb + OFF_VH + rv * AV_STR + cv * 16, v_g + gv);
    }
}

__global__ __launch_bounds__(ATHREADS, 2)
void attn_kernel(const __half* __restrict__ q_g, const __half* __restrict__ k_g,
                 const __half* __restrict__ v_g, __half* __restrict__ c_g)
{
    extern __shared__ __align__(128) uint8_t sm_raw[];
    const uint32_t sb = smem_to_u32(sm_raw);
    const int tid = threadIdx.x;
    const int wid = tid >> 5, lid = tid & 31;
    const int g = lid >> 2, t = lid & 3;
    const int bh = blockIdx.y;
    const int b = bh >> 4, h = bh & 15;
    const int q0 = blockIdx.x * 64;
    const int lrow = lid & 15;
    const int lcolb = (lid >> 4) * 16;

    const size_t qoff = ((size_t)bh * TT + q0) * HD;
    #pragma unroll
    for (int i = 0; i < 4; ++i) {
        const int idx = tid + ATHREADS * i;     // 0..511
        const int r = idx >> 3, c2 = idx & 7;
        const size_t gq = qoff + (size_t)r * HD + c2 * 16;
        cp_async16(sb + r * AQ_STR + c2 * 32,      q_g + gq);
        cp_async16(sb + r * AQ_STR + c2 * 32 + 16, q_g + gq + 8);
    }
    load_kv_chunk(sb, 0, 0, bh, k_g, v_g, tid);
    CP_ASYNC_COMMIT();
    load_kv_chunk(sb, 1, 1, bh, k_g, v_g, tid);
    CP_ASYNC_COMMIT();

    float O[16][4];
    #pragma unroll
    for (int nv = 0; nv < 16; ++nv)
        #pragma unroll
        for (int q = 0; q < 4; ++q) O[nv][q] = 0.0f;
    float mr0 = -1e30f, mr1 = -1e30f, lr0 = 0.0f, lr1 = 0.0f;

    for (int c = 0; c < 32; ++c) {
        CP_ASYNC_WAIT(1);
        __syncthreads();
        const uint32_t kb = sb + OFF_KV + (c & 1) * KV_BUF;

        // ---- S = Q K^T (log2-domain scores) ----
        float S[8][4];
        #pragma unroll
        for (int j = 0; j < 8; ++j)
            #pragma unroll
            for (int q = 0; q < 4; ++q) S[j][q] = 0.0f;

        #pragma unroll
        for (int ks = 0; ks < 8; ++ks) {
            const uint32_t cb = ks * 32 + lcolb;
            uint32_t qf[4], kf[4][4];
            ldm4(qf, sb + (wid * 16 + lrow) * AQ_STR + cb);
            #pragma unroll
            for (int jp = 0; jp < 4; ++jp)
                ldm4(kf[jp], kb + (jp * 16 + lrow) * AQ_STR + cb);
            #pragma unroll
            for (int jp = 0; jp < 4; ++jp) {
                mma16816(S[2 * jp],     qf, kf[jp][0], kf[jp][2]);
                mma16816(S[2 * jp + 1], qf, kf[jp][1], kf[jp][3]);
            }
        }

        // ---- online softmax (base-2, ex2.approx) ----
        float mx0 = -1e30f, mx1 = -1e30f;
        #pragma unroll
        for (int j = 0; j < 8; ++j) {
            mx0 = fmaxf(mx0, fmaxf(S[j][0], S[j][1]));
            mx1 = fmaxf(mx1, fmaxf(S[j][2], S[j][3]));
        }
        mx0 = fmaxf(mx0, __shfl_xor_sync(0xffffffffu, mx0, 1));
        mx0 = fmaxf(mx0, __shfl_xor_sync(0xffffffffu, mx0, 2));
        mx1 = fmaxf(mx1, __shfl_xor_sync(0xffffffffu, mx1, 1));
        mx1 = fmaxf(mx1, __shfl_xor_sync(0xffffffffu, mx1, 2));
        const float mn0 = fmaxf(mr0, mx0), mn1 = fmaxf(mr1, mx1);
        const float cr0 = ex2(mr0 - mn0), cr1 = ex2(mr1 - mn1);
        mr0 = mn0; mr1 = mn1;
        float ls0 = 0.0f, ls1 = 0.0f;
        #pragma unroll
        for (int j = 0; j < 8; ++j) {
            S[j][0] = ex2(S[j][0] - mn0);
            S[j][1] = ex2(S[j][1] - mn0);
            S[j][2] = ex2(S[j][2] - mn1);
            S[j][3] = ex2(S[j][3] - mn1);
            ls0 += S[j][0] + S[j][1];
            ls1 += S[j][2] + S[j][3];
        }
        ls0 += __shfl_xor_sync(0xffffffffu, ls0, 1);
        ls0 += __shfl_xor_sync(0xffffffffu, ls0, 2);
        ls1 += __shfl_xor_sync(0xffffffffu, ls1, 1);
        ls1 += __shfl_xor_sync(0xffffffffu, ls1, 2);
        lr0 = lr0 * cr0 + ls0;
        lr1 = lr1 * cr1 + ls1;
        #pragma unroll
        for (int nv = 0; nv < 16; ++nv) {
            O[nv][0] *= cr0; O[nv][1] *= cr0;
            O[nv][2] *= cr1; O[nv][3] *= cr1;
        }

        // ---- P fragments (single fp16) ----
        uint32_t pf[4][4];
        #pragma unroll
        for (int kk = 0; kk < 4; ++kk) {
            pf[kk][0] = packhf(__float2half(S[2 * kk][0]),     __float2half(S[2 * kk][1]));
            pf[kk][1] = packhf(__float2half(S[2 * kk][2]),     __float2half(S[2 * kk][3]));
            pf[kk][2] = packhf(__float2half(S[2 * kk + 1][0]), __float2half(S[2 * kk + 1][1]));
            pf[kk][3] = packhf(__float2half(S[2 * kk + 1][2]), __float2half(S[2 * kk + 1][3]));
        }

        // ---- O += P V (1-pass) ----
        const uint32_t vb = kb + OFF_VH;
        #pragma unroll
        for (int kk = 0; kk < 4; ++kk) {
            const uint32_t cb = kk * 32 + lcolb;
            #pragma unroll
            for (int half = 0; half < 2; ++half) {
                uint32_t vf[4][4];
                #pragma unroll
                for (int u = 0; u < 4; ++u)
                    ldm4(vf[u], vb + ((half * 4 + u) * 16 + lrow) * AV_STR + cb);
                #pragma unroll
                for (int u = 0; u < 4; ++u) {
                    const int np = half * 4 + u;
                    mma16816(O[2 * np],     pf[kk], vf[u][0], vf[u][2]);
                    mma16816(O[2 * np + 1], pf[kk], vf[u][1], vf[u][3]);
                }
            }
        }

        __syncthreads();
        if (c + 2 < 32)
            load_kv_chunk(sb, c & 1, c + 2, bh, k_g, v_g, tid);
        CP_ASYNC_COMMIT();
    }

    // ---- epilogue: ctx single fp16 ----
    const float inv0 = 1.0f / lr0, inv1 = 1.0f / lr1;
    const int t0 = q0 + wid * 16 + g;
    const int t1 = t0 + 8;
    #pragma unroll
    for (int nv = 0; nv < 16; ++nv) {
        const int d = h * HD + nv * 8 + 2 * t;
        const size_t o0 = ((size_t)b * TT + t0) * DD + d;
        const size_t o1 = ((size_t)b * TT + t1) * DD + d;
        *(uint32_t*)(c_g + o0) =
            packhf(__float2half(O[nv][0] * inv0), __float2half(O[nv][1] * inv0));
        *(uint32_t*)(c_g + o1) =
            packhf(__float2half(O[nv][2] * inv1), __float2half(O[nv][3] * inv1));
    }
}

// ---------------------------------------------------------------------------
extern "C" void kernel_launch(void* const* d_in, const int* in_sizes, int n_in,
                              void* d_out, int out_size)
{
    const float* hs  = (const float*)d_in[0];
    const float* enc = (const float*)d_in[1];
    const float* Wq  = (const float*)d_in[2];
    const float* Wk  = (const float*)d_in[3];
    const float* Wv  = (const float*)d_in[4];
    const float* Wo  = (const float*)d_in[5];
    const float* cq  = (const float*)d_in[6];
    const float* sq  = (const float*)d_in[7];
    const float* ck  = (const float*)d_in[8];
    const float* sk  = (const float*)d_in[9];

    __half *hs_c, *enc_c, *wq_c, *wk_c, *wv_c, *wo_c;
    __half *q_c, *k_c, *v_c, *c_c;
    cudaGetSymbolAddress((void**)&hs_c,  g_hs);
    cudaGetSymbolAddress((void**)&enc_c, g_enc);
    cudaGetSymbolAddress((void**)&wq_c,  g_wq);
    cudaGetSymbolAddress((void**)&wk_c,  g_wk);
    cudaGetSymbolAddress((void**)&wv_c,  g_wv);
    cudaGetSymbolAddress((void**)&wo_c,  g_wo);
    cudaGetSymbolAddress((void**)&q_c, g_q);
    cudaGetSymbolAddress((void**)&k_c, g_k);
    cudaGetSymbolAddress((void**)&v_c, g_v);
    cudaGetSymbolAddress((void**)&c_c, g_c);

    {
        const size_t nblocks = TOT_E / 8192;   // 4096
        conv_all<<<(unsigned)nblocks, 256>>>(
            hs, enc, Wq, Wk, Wv, Wo, hs_c, enc_c, wq_c, wk_c, wv_c, wo_c);
    }

    cudaFuncSetAttribute(gemm_kernel<true>,
                         cudaFuncAttributeMaxDynamicSharedMemorySize, SMEM_GEMM);
    cudaFuncSetAttribute(gemm_kernel<false>,
                         cudaFuncAttributeMaxDynamicSharedMemorySize, SMEM_GEMM);
    cudaFuncSetAttribute(attn_kernel,
                         cudaFuncAttributeMaxDynamicSharedMemorySize, ATT_SMEM);

    // Q/K/V projections (+RoPE +QSCALE-fold, +head split, +V transpose)
    gemm_kernel<true><<<dim3(DD / 128, MM / 128, 3), GTHREADS, SMEM_GEMM>>>(
        hs_c, enc_c, wq_c, wk_c, wv_c,
        cq, sq, ck, sk, q_c, k_c, v_c, nullptr);

    // Attention (BR=64, 2 CTAs/SM, base-2 softmax)
    attn_kernel<<<dim3(TT / 64, BB * HH), ATHREADS, ATT_SMEM>>>(
        q_c, k_c, v_c, c_c);

    // Output projection (fp32 out)
    gemm_kernel<false><<<dim3(DD / 128, MM / 128, 1), GTHREADS, SMEM_GEMM>>>(
        c_c, nullptr, wo_c, nullptr, nullptr,
        nullptr, nullptr, nullptr, nullptr,
        nullptr, nullptr, nullptr, (float*)d_out);
}